// round 3
// baseline (speedup 1.0000x reference)
#include <cuda_runtime.h>
#include <math.h>

#define B_ 2
#define S_ 2048
#define E_ 1024
#define H_ 16
#define D_ 64
#define NE_ 8
#define M_ 4096      // B_*S_
#define NSLOT_ 8192  // M_*2

// ---------------- scratch (device globals; no dynamic alloc) ----------------
static __device__ float g_qin[M_ * E_];
static __device__ float g_q[M_ * E_];    // (B,H,S,D)
static __device__ float g_k[M_ * E_];    // (B,H,S,D)
static __device__ float g_v[M_ * E_];    // (B,H,S,D)
static __device__ float g_ctx[M_ * E_];  // (B,S,E)
static __device__ float g_res1[M_ * E_]; // x + attn_out
static __device__ float g_x1[M_ * E_];   // LN1 output
static __device__ float g_eo[NSLOT_ * E_]; // per-slot expert output (gated)
static __device__ int   g_topidx[NSLOT_];
static __device__ float g_topgate[NSLOT_];
static __device__ int   g_counts[NE_];
static __device__ int   g_fill[NE_];
static __device__ int   g_offsets[NE_ + 1];
static __device__ int   g_rows[NSLOT_];    // rowinfo = token*2 + slot
static __device__ int   g_slotpos[NSLOT_]; // token slot -> gathered row
static __device__ int   g_tile_e[160];
static __device__ int   g_tile_r0[160];
static __device__ int   g_ntiles;

// ---------------- RoPE ----------------
__global__ void rope_kernel(const float* __restrict__ x) {
    int idx = blockIdx.x * blockDim.x + threadIdx.x;
    if (idx >= M_ * E_ / 2) return;
    int t = idx >> 9;        // token (row of 512 pairs)
    int p = idx & 511;
    int h = p >> 5;
    int i = p & 31;
    int s = t & (S_ - 1);    // sequence position
    float inv_freq = powf(10000.0f, -(float)(2 * i) * (1.0f / 64.0f));
    float ang = (float)s * inv_freq;
    float sn, cs;
    sincosf(ang, &sn, &cs);
    size_t base = (size_t)t * E_ + h * 64 + 2 * i;
    float a = x[base], b = x[base + 1];
    g_qin[base]     = a * cs - b * sn;
    g_qin[base + 1] = a * sn + b * cs;
}

// ---------------- 64x64x16 fp32 GEMM core, double-buffered (C = A * B^T) ----
// Tiles padded to 68 floats/row: keeps 16B alignment for LDS.128 reads while
// cutting transpose-write STS bank conflicts from 4-way to 2-way.
__device__ __forceinline__ void compute_tile(const float As[16][68],
                                             const float Bs[16][68],
                                             float acc[4][4], int tx, int ty) {
#pragma unroll
    for (int kk = 0; kk < 16; kk++) {
        float4 a = *(const float4*)&As[kk][ty * 4];
        float4 b = *(const float4*)&Bs[kk][tx * 4];
        acc[0][0] += a.x * b.x; acc[0][1] += a.x * b.y;
        acc[0][2] += a.x * b.z; acc[0][3] += a.x * b.w;
        acc[1][0] += a.y * b.x; acc[1][1] += a.y * b.y;
        acc[1][2] += a.y * b.z; acc[1][3] += a.y * b.w;
        acc[2][0] += a.z * b.x; acc[2][1] += a.z * b.y;
        acc[2][2] += a.z * b.z; acc[2][3] += a.z * b.w;
        acc[3][0] += a.w * b.x; acc[3][1] += a.w * b.y;
        acc[3][2] += a.w * b.z; acc[3][3] += a.w * b.w;
    }
}

__device__ __forceinline__ void gemm_core(const float* aptr, const float* bptr,
                                          float acc[4][4],
                                          float As[2][16][68], float Bs[2][16][68],
                                          int lr, int lc, int tx, int ty) {
    // prologue: fill buffer 0
    float4 av = *(const float4*)(aptr);
    float4 bv = *(const float4*)(bptr);
    As[0][lc + 0][lr] = av.x; As[0][lc + 1][lr] = av.y;
    As[0][lc + 2][lr] = av.z; As[0][lc + 3][lr] = av.w;
    Bs[0][lc + 0][lr] = bv.x; Bs[0][lc + 1][lr] = bv.y;
    Bs[0][lc + 2][lr] = bv.z; Bs[0][lc + 3][lr] = bv.w;
    __syncthreads();
    int buf = 0;
    for (int k0 = 16; k0 < E_; k0 += 16) {
        // issue next slice's loads; latency hidden by the FMAs below
        float4 av2 = *(const float4*)(aptr + k0);
        float4 bv2 = *(const float4*)(bptr + k0);
        compute_tile(As[buf], Bs[buf], acc, tx, ty);
        int nb = buf ^ 1;   // last read before the previous barrier -> safe to fill
        As[nb][lc + 0][lr] = av2.x; As[nb][lc + 1][lr] = av2.y;
        As[nb][lc + 2][lr] = av2.z; As[nb][lc + 3][lr] = av2.w;
        Bs[nb][lc + 0][lr] = bv2.x; Bs[nb][lc + 1][lr] = bv2.y;
        Bs[nb][lc + 2][lr] = bv2.z; Bs[nb][lc + 3][lr] = bv2.w;
        __syncthreads();
        buf = nb;
    }
    compute_tile(As[buf], Bs[buf], acc, tx, ty);
}

// ---------------- QKV projection ----------------
__global__ __launch_bounds__(256) void qkv_gemm(const float* __restrict__ x,
                                                const float* __restrict__ W,
                                                const float* __restrict__ bias) {
    __shared__ float As[2][16][68], Bs[2][16][68];
    int tid = threadIdx.x, tx = tid & 15, ty = tid >> 4;
    int n0 = blockIdx.x * 64, m0 = blockIdx.y * 64;
    int lr = tid >> 2, lc = (tid & 3) * 4;
    const float* A = (n0 < 2 * E_) ? g_qin : x; // q,k use rope(x); v uses x
    const float* aptr = A + (size_t)(m0 + lr) * E_ + lc;
    const float* bptr = W + (size_t)(n0 + lr) * E_ + lc;
    float acc[4][4] = {};
    gemm_core(aptr, bptr, acc, As, Bs, lr, lc, tx, ty);
    int which = n0 >> 10;
    float* dst = which == 0 ? g_q : (which == 1 ? g_k : g_v);
#pragma unroll
    for (int i2 = 0; i2 < 4; i2++) {
        int m = m0 + ty * 4 + i2;
        int b = m >> 11, s = m & 2047;
#pragma unroll
        for (int j = 0; j < 4; j++) {
            int o = n0 + tx * 4 + j;
            int e = o & 1023;
            int h = e >> 6, d = e & 63;
            dst[(((size_t)(b * H_ + h)) * S_ + s) * D_ + d] = acc[i2][j] + bias[o];
        }
    }
}

// ---------------- causal flash attention ----------------
// grid (S/32, B*H), 256 threads. Q tile 32 rows, K/V tile 64. 40KB smem.
__global__ __launch_bounds__(256) void attn_kernel() {
    __shared__ float Kt[64][64]; // K^T during scores; rows 0..31 reused as P
    __shared__ float Vs[64][64];
    __shared__ float Qs[32][64];
    int bh = blockIdx.y, qt = blockIdx.x;
    int q0 = qt * 32;
    const float* qb = g_q + (size_t)bh * S_ * D_;
    const float* kb = g_k + (size_t)bh * S_ * D_;
    const float* vb = g_v + (size_t)bh * S_ * D_;
    int tid = threadIdx.x;
    {
        int r = tid >> 3, c = (tid & 7) * 8;
        const float4* src = (const float4*)(qb + (size_t)(q0 + r) * 64 + c);
        *(float4*)&Qs[r][c]     = src[0];
        *(float4*)&Qs[r][c + 4] = src[1];
    }
    int r = tid >> 3, g = tid & 7;
    int qg = q0 + r;
    float m = -1e30f, l = 0.0f;
    float acc[8] = {};
    for (int kt0 = 0; kt0 < q0 + 32; kt0 += 64) {
        int j = tid >> 2, ds = (tid & 3) * 16;
        float4 k4[4], v4[4];
        const float4* kp = (const float4*)(kb + (size_t)(kt0 + j) * 64 + ds);
        const float4* vp = (const float4*)(vb + (size_t)(kt0 + j) * 64 + ds);
#pragma unroll
        for (int c = 0; c < 4; c++) { k4[c] = kp[c]; v4[c] = vp[c]; }
        __syncthreads();
#pragma unroll
        for (int c = 0; c < 4; c++) {
            *(float4*)&Vs[j][ds + c * 4] = v4[c];
            Kt[ds + 4 * c + 0][j] = k4[c].x;
            Kt[ds + 4 * c + 1][j] = k4[c].y;
            Kt[ds + 4 * c + 2][j] = k4[c].z;
            Kt[ds + 4 * c + 3][j] = k4[c].w;
        }
        __syncthreads();
        // scores: thread owns cols [g*8, g*8+8)
        float sc[8] = {};
#pragma unroll 16
        for (int d = 0; d < 64; d++) {
            float qv = Qs[r][d];
            float4 kA = *(const float4*)&Kt[d][g * 8];
            float4 kB = *(const float4*)&Kt[d][g * 8 + 4];
            sc[0] += qv * kA.x; sc[1] += qv * kA.y;
            sc[2] += qv * kA.z; sc[3] += qv * kA.w;
            sc[4] += qv * kB.x; sc[5] += qv * kB.y;
            sc[6] += qv * kB.z; sc[7] += qv * kB.w;
        }
        float mt = -1e30f;
#pragma unroll
        for (int jj = 0; jj < 8; jj++) {
            int kgl = kt0 + g * 8 + jj;
            sc[jj] = (kgl <= qg) ? sc[jj] * 0.125f : -1e30f;
            mt = fmaxf(mt, sc[jj]);
        }
#pragma unroll
        for (int o = 1; o < 8; o <<= 1)
            mt = fmaxf(mt, __shfl_xor_sync(0xffffffffu, mt, o));
        float mnew = fmaxf(m, mt);
        float corr = __expf(m - mnew);
        float pv[8];
        float ps = 0.0f;
#pragma unroll
        for (int jj = 0; jj < 8; jj++) { pv[jj] = __expf(sc[jj] - mnew); ps += pv[jj]; }
#pragma unroll
        for (int o = 1; o < 8; o <<= 1)
            ps += __shfl_xor_sync(0xffffffffu, ps, o);
        l = l * corr + ps;
#pragma unroll
        for (int dd = 0; dd < 8; dd++) acc[dd] *= corr;
        m = mnew;
        __syncthreads();            // all warps done reading Kt
#pragma unroll
        for (int jj = 0; jj < 8; jj++) Kt[r][g * 8 + jj] = pv[jj]; // P overlay
        __syncwarp();               // P row written/read by same warp
#pragma unroll 16
        for (int jx = 0; jx < 64; jx++) {
            float p = Kt[r][jx];
            float4 vA = *(const float4*)&Vs[jx][g * 8];
            float4 vB = *(const float4*)&Vs[jx][g * 8 + 4];
            acc[0] += p * vA.x; acc[1] += p * vA.y;
            acc[2] += p * vA.z; acc[3] += p * vA.w;
            acc[4] += p * vB.x; acc[5] += p * vB.y;
            acc[6] += p * vB.z; acc[7] += p * vB.w;
        }
    }
    float inv = 1.0f / l;
    int b = bh >> 4, h = bh & 15;
    float* op = g_ctx + ((size_t)(b * S_ + qg)) * E_ + h * 64 + g * 8;
    float4 o0 = make_float4(acc[0] * inv, acc[1] * inv, acc[2] * inv, acc[3] * inv);
    float4 o1 = make_float4(acc[4] * inv, acc[5] * inv, acc[6] * inv, acc[7] * inv);
    *(float4*)(op)     = o0;
    *(float4*)(op + 4) = o1;
}

// ---------------- out-proj GEMM + residual ----------------
__global__ __launch_bounds__(256) void outproj_gemm(const float* __restrict__ x,
                                                    const float* __restrict__ W,
                                                    const float* __restrict__ bias) {
    __shared__ float As[2][16][68], Bs[2][16][68];
    int tid = threadIdx.x, tx = tid & 15, ty = tid >> 4;
    int n0 = blockIdx.x * 64, m0 = blockIdx.y * 64;
    int lr = tid >> 2, lc = (tid & 3) * 4;
    const float* aptr = g_ctx + (size_t)(m0 + lr) * E_ + lc;
    const float* bptr = W + (size_t)(n0 + lr) * E_ + lc;
    float acc[4][4] = {};
    gemm_core(aptr, bptr, acc, As, Bs, lr, lc, tx, ty);
#pragma unroll
    for (int i2 = 0; i2 < 4; i2++) {
        int mr = m0 + ty * 4 + i2;
#pragma unroll
        for (int j = 0; j < 4; j++) {
            int o = n0 + tx * 4 + j;
            size_t idx = (size_t)mr * E_ + o;
            g_res1[idx] = acc[i2][j] + bias[o] + x[idx];
        }
    }
}

// ---------------- block reduction helper ----------------
__device__ __forceinline__ float2 block_reduce_sum2(float s1, float s2) {
    __shared__ float r1[8], r2[8];
#pragma unroll
    for (int o = 16; o; o >>= 1) {
        s1 += __shfl_xor_sync(0xffffffffu, s1, o);
        s2 += __shfl_xor_sync(0xffffffffu, s2, o);
    }
    int w = threadIdx.x >> 5;
    if ((threadIdx.x & 31) == 0) { r1[w] = s1; r2[w] = s2; }
    __syncthreads();
    float t1 = 0, t2 = 0;
#pragma unroll
    for (int i = 0; i < 8; i++) { t1 += r1[i]; t2 += r2[i]; }
    return make_float2(t1, t2);
}

// ---------------- LN1 ----------------
__global__ __launch_bounds__(256) void ln1_kernel(const float* __restrict__ w,
                                                  const float* __restrict__ bb) {
    int t = blockIdx.x, tid = threadIdx.x;
    float4 v = ((const float4*)(g_res1 + (size_t)t * E_))[tid];
    float s1 = v.x + v.y + v.z + v.w;
    float s2 = v.x * v.x + v.y * v.y + v.z * v.z + v.w * v.w;
    float2 tt = block_reduce_sum2(s1, s2);
    float mu = tt.x * (1.0f / E_);
    float var = tt.y * (1.0f / E_) - mu * mu;
    float inv = rsqrtf(var + 1e-5f);
    float4 wv = ((const float4*)w)[tid];
    float4 bv = ((const float4*)bb)[tid];
    float4 o;
    o.x = (v.x - mu) * inv * wv.x + bv.x;
    o.y = (v.y - mu) * inv * wv.y + bv.y;
    o.z = (v.z - mu) * inv * wv.z + bv.z;
    o.w = (v.w - mu) * inv * wv.w + bv.w;
    ((float4*)(g_x1 + (size_t)t * E_))[tid] = o;
}

// ---------------- routing ----------------
__global__ void init_kernel() {
    int i = threadIdx.x;
    if (i < NE_) { g_counts[i] = 0; g_fill[i] = 0; }
}

__global__ __launch_bounds__(256) void gate_kernel(const float* __restrict__ gw,
                                                   const float* __restrict__ gb) {
    int t = blockIdx.x, tid = threadIdx.x;
    int w = tid >> 5, l = tid & 31;
    const float* xr = g_x1 + (size_t)t * E_;
    const float* wr = gw + (size_t)w * E_;
    float s = 0.0f;
    for (int k = l; k < E_; k += 32) s += xr[k] * wr[k];
#pragma unroll
    for (int o = 16; o; o >>= 1) s += __shfl_xor_sync(0xffffffffu, s, o);
    __shared__ float lg[NE_];
    if (l == 0) lg[w] = s + gb[w];
    __syncthreads();
    if (tid == 0) {
        float mx = lg[0];
        for (int e = 1; e < NE_; e++) mx = fmaxf(mx, lg[e]);
        float ex[NE_], sum = 0.0f;
        for (int e = 0; e < NE_; e++) { ex[e] = __expf(lg[e] - mx); sum += ex[e]; }
        float invs = 1.0f / sum;
        int i0 = 0;
        for (int e = 1; e < NE_; e++) if (lg[e] > lg[i0]) i0 = e;
        int i1 = (i0 == 0) ? 1 : 0;
        for (int e = 0; e < NE_; e++) if (e != i0 && lg[e] > lg[i1]) i1 = e;
        g_topidx[t * 2] = i0; g_topidx[t * 2 + 1] = i1;
        g_topgate[t * 2] = ex[i0] * invs; g_topgate[t * 2 + 1] = ex[i1] * invs;
        atomicAdd(&g_counts[i0], 1);
        atomicAdd(&g_counts[i1], 1);
    }
}

__global__ void offsets_kernel() {
    if (threadIdx.x == 0 && blockIdx.x == 0) {
        int off = 0, tt = 0;
        for (int e = 0; e < NE_; e++) {
            g_offsets[e] = off;
            int c = g_counts[e];
            int nt = (c + 63) >> 6;
            for (int i = 0; i < nt; i++) { g_tile_e[tt] = e; g_tile_r0[tt] = off + i * 64; tt++; }
            off += c;
        }
        g_offsets[NE_] = off;
        g_ntiles = tt;
    }
}

__global__ void scatter_kernel() {
    int sidx = blockIdx.x * blockDim.x + threadIdx.x;
    if (sidx >= NSLOT_) return;
    int e = g_topidx[sidx];
    int pos = g_offsets[e] + atomicAdd(&g_fill[e], 1);
    g_rows[pos] = sidx;
    g_slotpos[sidx] = pos;
}

// ---------------- grouped expert GEMM (top-2 only) ----------------
__global__ __launch_bounds__(256) void expert_gemm(const float* __restrict__ eW,
                                                   const float* __restrict__ eB) {
    int bt = blockIdx.y;
    if (bt >= g_ntiles) return;
    __shared__ float As[2][16][68], Bs[2][16][68];
    int tid = threadIdx.x, tx = tid & 15, ty = tid >> 4;
    int n0 = blockIdx.x * 64;
    int e = g_tile_e[bt], r0 = g_tile_r0[bt], rend = g_offsets[e + 1];
    int lr = tid >> 2, lc = (tid & 3) * 4;
    int rg = r0 + lr;
    if (rg >= rend) rg = rend - 1;
    int tok = g_rows[rg] >> 1;
    const float* aptr = g_x1 + (size_t)tok * E_ + lc;
    const float* bptr = eW + (size_t)e * E_ * E_ + (size_t)(n0 + lr) * E_ + lc;
    float acc[4][4] = {};
    gemm_core(aptr, bptr, acc, As, Bs, lr, lc, tx, ty);
#pragma unroll
    for (int i2 = 0; i2 < 4; i2++) {
        int rgi = r0 + ty * 4 + i2;
        if (rgi < rend) {
            int info = g_rows[rgi];
            float gt = g_topgate[info];
#pragma unroll
            for (int j = 0; j < 4; j++) {
                int o = n0 + tx * 4 + j;
                g_eo[(size_t)rgi * E_ + o] = (acc[i2][j] + eB[e * E_ + o]) * gt;
            }
        }
    }
}

// ---------------- combine + LN2 -> d_out ----------------
__global__ __launch_bounds__(256) void moe_ln2_kernel(const float* __restrict__ w,
                                                      const float* __restrict__ bb,
                                                      float* __restrict__ out) {
    int t = blockIdx.x, tid = threadIdx.x;
    int p0 = g_slotpos[t * 2], p1 = g_slotpos[t * 2 + 1];
    float4 a  = ((const float4*)(g_x1 + (size_t)t * E_))[tid];
    float4 e0 = ((const float4*)(g_eo + (size_t)p0 * E_))[tid];
    float4 e1 = ((const float4*)(g_eo + (size_t)p1 * E_))[tid];
    float4 v = make_float4(a.x + e0.x + e1.x, a.y + e0.y + e1.y,
                           a.z + e0.z + e1.z, a.w + e0.w + e1.w);
    float s1 = v.x + v.y + v.z + v.w;
    float s2 = v.x * v.x + v.y * v.y + v.z * v.z + v.w * v.w;
    float2 tt = block_reduce_sum2(s1, s2);
    float mu = tt.x * (1.0f / E_);
    float var = tt.y * (1.0f / E_) - mu * mu;
    float inv = rsqrtf(var + 1e-5f);
    float4 wv = ((const float4*)w)[tid];
    float4 bv = ((const float4*)bb)[tid];
    float4 o;
    o.x = (v.x - mu) * inv * wv.x + bv.x;
    o.y = (v.y - mu) * inv * wv.y + bv.y;
    o.z = (v.z - mu) * inv * wv.z + bv.z;
    o.w = (v.w - mu) * inv * wv.w + bv.w;
    ((float4*)(out + (size_t)t * E_))[tid] = o;
}

// ---------------- launch ----------------
extern "C" void kernel_launch(void* const* d_in, const int* in_sizes, int n_in,
                              void* d_out, int out_size) {
    (void)in_sizes; (void)n_in; (void)out_size;
    const float* x      = (const float*)d_in[0];
    const float* in_w   = (const float*)d_in[1];
    const float* in_b   = (const float*)d_in[2];
    const float* ow     = (const float*)d_in[3];
    const float* ob     = (const float*)d_in[4];
    const float* gw     = (const float*)d_in[5];
    const float* gb     = (const float*)d_in[6];
    const float* ew     = (const float*)d_in[7];
    const float* eb     = (const float*)d_in[8];
    const float* ln1w   = (const float*)d_in[9];
    const float* ln1b   = (const float*)d_in[10];
    const float* ln2w   = (const float*)d_in[11];
    const float* ln2b   = (const float*)d_in[12];
    float* out = (float*)d_out;

    init_kernel<<<1, 32>>>();
    rope_kernel<<<(M_ * E_ / 2 + 255) / 256, 256>>>(x);
    qkv_gemm<<<dim3(48, 64), 256>>>(x, in_w, in_b);
    attn_kernel<<<dim3(S_ / 32, B_ * H_), 256>>>();
    outproj_gemm<<<dim3(16, 64), 256>>>(x, ow, ob);
    ln1_kernel<<<M_, 256>>>(ln1w, ln1b);
    gate_kernel<<<M_, 256>>>(gw, gb);
    offsets_kernel<<<1, 32>>>();
    scatter_kernel<<<NSLOT_ / 256, 256>>>();
    expert_gemm<<<dim3(16, 144), 256>>>(ew, eb);
    moe_ln2_kernel<<<M_, 256>>>(ln2w, ln2b, out);
}

// round 9
// speedup vs baseline: 1.3490x; 1.3490x over previous
#include <cuda_runtime.h>
#include <math.h>

#define B_ 2
#define S_ 2048
#define E_ 1024
#define H_ 16
#define D_ 64
#define NE_ 8
#define M_ 4096      // B_*S_
#define NSLOT_ 8192  // M_*2

// ---------------- scratch (device globals; no dynamic alloc) ----------------
static __device__ float g_qin[M_ * E_];
static __device__ float g_q[M_ * E_];    // (B,H,S,D)
static __device__ float g_k[M_ * E_];    // (B,H,S,D)
static __device__ float g_v[M_ * E_];    // (B,H,S,D)
static __device__ float g_ctx[M_ * E_];  // (B,S,E)
static __device__ float g_res1[M_ * E_]; // x + attn_out
static __device__ float g_x1[M_ * E_];   // LN1 output
static __device__ float g_eo[NSLOT_ * E_]; // per-slot expert output (gated)
static __device__ int   g_topidx[NSLOT_];
static __device__ float g_topgate[NSLOT_];
static __device__ int   g_counts[NE_];
static __device__ int   g_fill[NE_];
static __device__ int   g_offsets[NE_ + 1];
static __device__ int   g_rows[NSLOT_];    // rowinfo = token*2 + slot
static __device__ int   g_slotpos[NSLOT_]; // token slot -> gathered row
static __device__ int   g_tile_e[160];
static __device__ int   g_tile_r0[160];
static __device__ int   g_ntiles;

// ---------------- RoPE ----------------
__global__ void rope_kernel(const float* __restrict__ x) {
    int idx = blockIdx.x * blockDim.x + threadIdx.x;
    if (idx >= M_ * E_ / 2) return;
    int t = idx >> 9;        // token (row of 512 pairs)
    int p = idx & 511;
    int h = p >> 5;
    int i = p & 31;
    int s = t & (S_ - 1);    // sequence position
    float inv_freq = powf(10000.0f, -(float)(2 * i) * (1.0f / 64.0f));
    float ang = (float)s * inv_freq;
    float sn, cs;
    sincosf(ang, &sn, &cs);
    size_t base = (size_t)t * E_ + h * 64 + 2 * i;
    float a = x[base], b = x[base + 1];
    g_qin[base]     = a * cs - b * sn;
    g_qin[base + 1] = a * sn + b * cs;
}

// ============ 128x128x8 fp32 GEMM core, double-buffered (C = A * B^T) =======
// Smem tiles stored K-outer as [8][136] (136 keeps 16B alignment for LDS.128
// and bounds transpose-store conflicts to 2-way). 8x8 microtile per thread:
// 4 LDS.128 per 64 FMA -> FMA-issue bound.
__device__ __forceinline__ void ctile128(const float As[8][136], const float Bs[8][136],
                                         float acc[8][8], int tx, int ty) {
#pragma unroll
    for (int kk = 0; kk < 8; kk++) {
        float a[8], b[8];
        *(float4*)&a[0] = *(const float4*)&As[kk][ty * 8];
        *(float4*)&a[4] = *(const float4*)&As[kk][ty * 8 + 4];
        *(float4*)&b[0] = *(const float4*)&Bs[kk][tx * 8];
        *(float4*)&b[4] = *(const float4*)&Bs[kk][tx * 8 + 4];
#pragma unroll
        for (int i = 0; i < 8; i++)
#pragma unroll
            for (int j = 0; j < 8; j++) acc[i][j] += a[i] * b[j];
    }
}

__device__ __forceinline__ void gemm128_core(const float* aptr, const float* bptr,
                                             float acc[8][8],
                                             float As[2][8][136], float Bs[2][8][136],
                                             int lrow, int lcol, int tx, int ty) {
    // prologue: fill buffer 0
    {
        float4 av = *(const float4*)(aptr);
        float4 bv = *(const float4*)(bptr);
        As[0][lcol + 0][lrow] = av.x; As[0][lcol + 1][lrow] = av.y;
        As[0][lcol + 2][lrow] = av.z; As[0][lcol + 3][lrow] = av.w;
        Bs[0][lcol + 0][lrow] = bv.x; Bs[0][lcol + 1][lrow] = bv.y;
        Bs[0][lcol + 2][lrow] = bv.z; Bs[0][lcol + 3][lrow] = bv.w;
    }
    __syncthreads();
    int buf = 0;
    for (int k0 = 8; k0 < E_; k0 += 8) {
        float4 av = *(const float4*)(aptr + k0);   // latency hidden by ctile
        float4 bv = *(const float4*)(bptr + k0);
        ctile128(As[buf], Bs[buf], acc, tx, ty);
        int nb = buf ^ 1;
        As[nb][lcol + 0][lrow] = av.x; As[nb][lcol + 1][lrow] = av.y;
        As[nb][lcol + 2][lrow] = av.z; As[nb][lcol + 3][lrow] = av.w;
        Bs[nb][lcol + 0][lrow] = bv.x; Bs[nb][lcol + 1][lrow] = bv.y;
        Bs[nb][lcol + 2][lrow] = bv.z; Bs[nb][lcol + 3][lrow] = bv.w;
        __syncthreads();
        buf = nb;
    }
    ctile128(As[buf], Bs[buf], acc, tx, ty);
}

// ---------------- QKV projection ----------------
__global__ __launch_bounds__(256, 2) void qkv_gemm(const float* __restrict__ x,
                                                   const float* __restrict__ W,
                                                   const float* __restrict__ bias) {
    __shared__ float As[2][8][136], Bs[2][8][136];
    int tid = threadIdx.x, tx = tid & 15, ty = tid >> 4;
    int n0 = blockIdx.x * 128, m0 = blockIdx.y * 128;
    int lrow = tid >> 1, lcol = (tid & 1) * 4;
    const float* A = (n0 < 2 * E_) ? g_qin : x; // q,k use rope(x); v uses x
    const float* aptr = A + (size_t)(m0 + lrow) * E_ + lcol;
    const float* bptr = W + (size_t)(n0 + lrow) * E_ + lcol;
    float acc[8][8] = {};
    gemm128_core(aptr, bptr, acc, As, Bs, lrow, lcol, tx, ty);
    int which = n0 >> 10;
    float* dst = which == 0 ? g_q : (which == 1 ? g_k : g_v);
    int o0 = n0 + tx * 8;
    float bsr[8];
#pragma unroll
    for (int j = 0; j < 8; j++) bsr[j] = bias[o0 + j];
    int e = o0 & 1023;
    int h = e >> 6, d = e & 63;   // 8|64 so the 8-col strip never crosses a head
#pragma unroll
    for (int i = 0; i < 8; i++) {
        int m = m0 + ty * 8 + i;
        int b = m >> 11, s = m & 2047;
        float* p = dst + (((size_t)(b * H_ + h)) * S_ + s) * D_ + d;
        float4 w0 = make_float4(acc[i][0] + bsr[0], acc[i][1] + bsr[1],
                                acc[i][2] + bsr[2], acc[i][3] + bsr[3]);
        float4 w1 = make_float4(acc[i][4] + bsr[4], acc[i][5] + bsr[5],
                                acc[i][6] + bsr[6], acc[i][7] + bsr[7]);
        *(float4*)(p)     = w0;
        *(float4*)(p + 4) = w1;
    }
}

// ---------------- causal flash attention ----------------
// grid (S/64, B*H), 256 threads. Q tile 64 rows (2 per thread), K/V tile 64.
// 48KB smem. Thread (r,g) handles q rows r, r+32 and k-cols [g*8, g*8+8).
__global__ __launch_bounds__(256) void attn_kernel() {
    __shared__ float Qs[64][64];
    __shared__ float Kt[64][64]; // K^T during scores; overlaid with P for PV
    __shared__ float Vs[64][64];
    int bh = blockIdx.y, qt = blockIdx.x;
    int q0 = qt * 64;
    const float* qb = g_q + (size_t)bh * S_ * D_;
    const float* kb = g_k + (size_t)bh * S_ * D_;
    const float* vb = g_v + (size_t)bh * S_ * D_;
    int tid = threadIdx.x;
    {
        int r = tid >> 2, c = (tid & 3) * 16;
        const float4* src = (const float4*)(qb + (size_t)(q0 + r) * 64 + c);
        *(float4*)&Qs[r][c]      = src[0];
        *(float4*)&Qs[r][c + 4]  = src[1];
        *(float4*)&Qs[r][c + 8]  = src[2];
        *(float4*)&Qs[r][c + 12] = src[3];
    }
    int r = tid >> 3, g = tid & 7;
    int qg0 = q0 + r, qg1 = q0 + r + 32;
    float m0v = -1e30f, l0 = 0.0f, m1v = -1e30f, l1 = 0.0f;
    float acc0[8] = {}, acc1[8] = {};
    for (int kt0 = 0; kt0 < q0 + 64; kt0 += 64) {
        int j = tid >> 2, ds = (tid & 3) * 16;
        float4 k4[4], v4[4];
        const float4* kp = (const float4*)(kb + (size_t)(kt0 + j) * 64 + ds);
        const float4* vp = (const float4*)(vb + (size_t)(kt0 + j) * 64 + ds);
#pragma unroll
        for (int c = 0; c < 4; c++) { k4[c] = kp[c]; v4[c] = vp[c]; }
        __syncthreads();   // prev iter done with Kt/Vs; iter0: Q visible
#pragma unroll
        for (int c = 0; c < 4; c++) {
            *(float4*)&Vs[j][ds + c * 4] = v4[c];
            Kt[ds + 4 * c + 0][j] = k4[c].x;
            Kt[ds + 4 * c + 1][j] = k4[c].y;
            Kt[ds + 4 * c + 2][j] = k4[c].z;
            Kt[ds + 4 * c + 3][j] = k4[c].w;
        }
        __syncthreads();
        // scores for both rows; Kt float4s shared
        float sc0[8] = {}, sc1[8] = {};
#pragma unroll 8
        for (int d = 0; d < 64; d++) {
            float qa = Qs[r][d], qc = Qs[r + 32][d];
            float4 kA = *(const float4*)&Kt[d][g * 8];
            float4 kB = *(const float4*)&Kt[d][g * 8 + 4];
            sc0[0] += qa * kA.x; sc0[1] += qa * kA.y;
            sc0[2] += qa * kA.z; sc0[3] += qa * kA.w;
            sc0[4] += qa * kB.x; sc0[5] += qa * kB.y;
            sc0[6] += qa * kB.z; sc0[7] += qa * kB.w;
            sc1[0] += qc * kA.x; sc1[1] += qc * kA.y;
            sc1[2] += qc * kA.z; sc1[3] += qc * kA.w;
            sc1[4] += qc * kB.x; sc1[5] += qc * kB.y;
            sc1[6] += qc * kB.z; sc1[7] += qc * kB.w;
        }
        float mt0 = -1e30f, mt1 = -1e30f;
#pragma unroll
        for (int jj = 0; jj < 8; jj++) {
            int kgl = kt0 + g * 8 + jj;
            sc0[jj] = (kgl <= qg0) ? sc0[jj] * 0.125f : -1e30f;
            sc1[jj] = (kgl <= qg1) ? sc1[jj] * 0.125f : -1e30f;
            mt0 = fmaxf(mt0, sc0[jj]);
            mt1 = fmaxf(mt1, sc1[jj]);
        }
#pragma unroll
        for (int o = 1; o < 8; o <<= 1) {
            mt0 = fmaxf(mt0, __shfl_xor_sync(0xffffffffu, mt0, o));
            mt1 = fmaxf(mt1, __shfl_xor_sync(0xffffffffu, mt1, o));
        }
        float mn0 = fmaxf(m0v, mt0), mn1 = fmaxf(m1v, mt1);
        float cr0 = __expf(m0v - mn0), cr1 = __expf(m1v - mn1);
        float pv0[8], pv1[8];
        float ps0 = 0.0f, ps1 = 0.0f;
#pragma unroll
        for (int jj = 0; jj < 8; jj++) {
            pv0[jj] = __expf(sc0[jj] - mn0); ps0 += pv0[jj];
            pv1[jj] = __expf(sc1[jj] - mn1); ps1 += pv1[jj];
        }
#pragma unroll
        for (int o = 1; o < 8; o <<= 1) {
            ps0 += __shfl_xor_sync(0xffffffffu, ps0, o);
            ps1 += __shfl_xor_sync(0xffffffffu, ps1, o);
        }
        l0 = l0 * cr0 + ps0;
        l1 = l1 * cr1 + ps1;
#pragma unroll
        for (int dd = 0; dd < 8; dd++) { acc0[dd] *= cr0; acc1[dd] *= cr1; }
        m0v = mn0; m1v = mn1;
        __syncthreads();            // all warps done reading Kt as K^T
#pragma unroll
        for (int jj = 0; jj < 8; jj++) {
            Kt[r][g * 8 + jj]      = pv0[jj];  // P overlay
            Kt[r + 32][g * 8 + jj] = pv1[jj];
        }
        __syncwarp();               // both P rows written/read by same warp
#pragma unroll 8
        for (int jx = 0; jx < 64; jx++) {
            float p0 = Kt[r][jx], p1 = Kt[r + 32][jx];
            float4 vA = *(const float4*)&Vs[jx][g * 8];
            float4 vB = *(const float4*)&Vs[jx][g * 8 + 4];
            acc0[0] += p0 * vA.x; acc0[1] += p0 * vA.y;
            acc0[2] += p0 * vA.z; acc0[3] += p0 * vA.w;
            acc0[4] += p0 * vB.x; acc0[5] += p0 * vB.y;
            acc0[6] += p0 * vB.z; acc0[7] += p0 * vB.w;
            acc1[0] += p1 * vA.x; acc1[1] += p1 * vA.y;
            acc1[2] += p1 * vA.z; acc1[3] += p1 * vA.w;
            acc1[4] += p1 * vB.x; acc1[5] += p1 * vB.y;
            acc1[6] += p1 * vB.z; acc1[7] += p1 * vB.w;
        }
    }
    float in0 = 1.0f / l0, in1 = 1.0f / l1;
    int b = bh >> 4, h = bh & 15;
    float* op0 = g_ctx + ((size_t)(b * S_ + qg0)) * E_ + h * 64 + g * 8;
    float* op1 = g_ctx + ((size_t)(b * S_ + qg1)) * E_ + h * 64 + g * 8;
    *(float4*)(op0)     = make_float4(acc0[0] * in0, acc0[1] * in0, acc0[2] * in0, acc0[3] * in0);
    *(float4*)(op0 + 4) = make_float4(acc0[4] * in0, acc0[5] * in0, acc0[6] * in0, acc0[7] * in0);
    *(float4*)(op1)     = make_float4(acc1[0] * in1, acc1[1] * in1, acc1[2] * in1, acc1[3] * in1);
    *(float4*)(op1 + 4) = make_float4(acc1[4] * in1, acc1[5] * in1, acc1[6] * in1, acc1[7] * in1);
}

// ---------------- out-proj GEMM + residual ----------------
__global__ __launch_bounds__(256, 2) void outproj_gemm(const float* __restrict__ x,
                                                       const float* __restrict__ W,
                                                       const float* __restrict__ bias) {
    __shared__ float As[2][8][136], Bs[2][8][136];
    int tid = threadIdx.x, tx = tid & 15, ty = tid >> 4;
    int n0 = blockIdx.x * 128, m0 = blockIdx.y * 128;
    int lrow = tid >> 1, lcol = (tid & 1) * 4;
    const float* aptr = g_ctx + (size_t)(m0 + lrow) * E_ + lcol;
    const float* bptr = W + (size_t)(n0 + lrow) * E_ + lcol;
    float acc[8][8] = {};
    gemm128_core(aptr, bptr, acc, As, Bs, lrow, lcol, tx, ty);
    int o0 = n0 + tx * 8;
    float bsr[8];
#pragma unroll
    for (int j = 0; j < 8; j++) bsr[j] = bias[o0 + j];
#pragma unroll
    for (int i = 0; i < 8; i++) {
        int mr = m0 + ty * 8 + i;
        size_t idx = (size_t)mr * E_ + o0;
        float4 x0 = *(const float4*)(x + idx);
        float4 x1 = *(const float4*)(x + idx + 4);
        float4 w0 = make_float4(acc[i][0] + bsr[0] + x0.x, acc[i][1] + bsr[1] + x0.y,
                                acc[i][2] + bsr[2] + x0.z, acc[i][3] + bsr[3] + x0.w);
        float4 w1 = make_float4(acc[i][4] + bsr[4] + x1.x, acc[i][5] + bsr[5] + x1.y,
                                acc[i][6] + bsr[6] + x1.z, acc[i][7] + bsr[7] + x1.w);
        *(float4*)(g_res1 + idx)     = w0;
        *(float4*)(g_res1 + idx + 4) = w1;
    }
}

// ---------------- block reduction helper ----------------
__device__ __forceinline__ float2 block_reduce_sum2(float s1, float s2) {
    __shared__ float r1[8], r2[8];
#pragma unroll
    for (int o = 16; o; o >>= 1) {
        s1 += __shfl_xor_sync(0xffffffffu, s1, o);
        s2 += __shfl_xor_sync(0xffffffffu, s2, o);
    }
    int w = threadIdx.x >> 5;
    if ((threadIdx.x & 31) == 0) { r1[w] = s1; r2[w] = s2; }
    __syncthreads();
    float t1 = 0, t2 = 0;
#pragma unroll
    for (int i = 0; i < 8; i++) { t1 += r1[i]; t2 += r2[i]; }
    return make_float2(t1, t2);
}

// ---------------- LN1 ----------------
__global__ __launch_bounds__(256) void ln1_kernel(const float* __restrict__ w,
                                                  const float* __restrict__ bb) {
    int t = blockIdx.x, tid = threadIdx.x;
    float4 v = ((const float4*)(g_res1 + (size_t)t * E_))[tid];
    float s1 = v.x + v.y + v.z + v.w;
    float s2 = v.x * v.x + v.y * v.y + v.z * v.z + v.w * v.w;
    float2 tt = block_reduce_sum2(s1, s2);
    float mu = tt.x * (1.0f / E_);
    float var = tt.y * (1.0f / E_) - mu * mu;
    float inv = rsqrtf(var + 1e-5f);
    float4 wv = ((const float4*)w)[tid];
    float4 bv = ((const float4*)bb)[tid];
    float4 o;
    o.x = (v.x - mu) * inv * wv.x + bv.x;
    o.y = (v.y - mu) * inv * wv.y + bv.y;
    o.z = (v.z - mu) * inv * wv.z + bv.z;
    o.w = (v.w - mu) * inv * wv.w + bv.w;
    ((float4*)(g_x1 + (size_t)t * E_))[tid] = o;
}

// ---------------- routing ----------------
__global__ void init_kernel() {
    int i = threadIdx.x;
    if (i < NE_) { g_counts[i] = 0; g_fill[i] = 0; }
}

__global__ __launch_bounds__(256) void gate_kernel(const float* __restrict__ gw,
                                                   const float* __restrict__ gb) {
    int t = blockIdx.x, tid = threadIdx.x;
    int w = tid >> 5, l = tid & 31;
    const float* xr = g_x1 + (size_t)t * E_;
    const float* wr = gw + (size_t)w * E_;
    float s = 0.0f;
    for (int k = l; k < E_; k += 32) s += xr[k] * wr[k];
#pragma unroll
    for (int o = 16; o; o >>= 1) s += __shfl_xor_sync(0xffffffffu, s, o);
    __shared__ float lg[NE_];
    if (l == 0) lg[w] = s + gb[w];
    __syncthreads();
    if (tid == 0) {
        float mx = lg[0];
        for (int e = 1; e < NE_; e++) mx = fmaxf(mx, lg[e]);
        float ex[NE_], sum = 0.0f;
        for (int e = 0; e < NE_; e++) { ex[e] = __expf(lg[e] - mx); sum += ex[e]; }
        float invs = 1.0f / sum;
        int i0 = 0;
        for (int e = 1; e < NE_; e++) if (lg[e] > lg[i0]) i0 = e;
        int i1 = (i0 == 0) ? 1 : 0;
        for (int e = 0; e < NE_; e++) if (e != i0 && lg[e] > lg[i1]) i1 = e;
        g_topidx[t * 2] = i0; g_topidx[t * 2 + 1] = i1;
        g_topgate[t * 2] = ex[i0] * invs; g_topgate[t * 2 + 1] = ex[i1] * invs;
        atomicAdd(&g_counts[i0], 1);
        atomicAdd(&g_counts[i1], 1);
    }
}

__global__ void offsets_kernel() {
    if (threadIdx.x == 0 && blockIdx.x == 0) {
        int off = 0, tt = 0;
        for (int e = 0; e < NE_; e++) {
            g_offsets[e] = off;
            int c = g_counts[e];
            int nt = (c + 127) >> 7;   // 128-row tiles
            for (int i = 0; i < nt; i++) { g_tile_e[tt] = e; g_tile_r0[tt] = off + i * 128; tt++; }
            off += c;
        }
        g_offsets[NE_] = off;
        g_ntiles = tt;
    }
}

__global__ void scatter_kernel() {
    int sidx = blockIdx.x * blockDim.x + threadIdx.x;
    if (sidx >= NSLOT_) return;
    int e = g_topidx[sidx];
    int pos = g_offsets[e] + atomicAdd(&g_fill[e], 1);
    g_rows[pos] = sidx;
    g_slotpos[sidx] = pos;
}

// ---------------- grouped expert GEMM (top-2 only) ----------------
__global__ __launch_bounds__(256, 2) void expert_gemm(const float* __restrict__ eW,
                                                      const float* __restrict__ eB) {
    int bt = blockIdx.y;
    if (bt >= g_ntiles) return;
    __shared__ float As[2][8][136], Bs[2][8][136];
    int tid = threadIdx.x, tx = tid & 15, ty = tid >> 4;
    int n0 = blockIdx.x * 128;
    int e = g_tile_e[bt], r0 = g_tile_r0[bt], rend = g_offsets[e + 1];
    int lrow = tid >> 1, lcol = (tid & 1) * 4;
    int rg = r0 + lrow;
    if (rg >= rend) rg = rend - 1;
    int tok = g_rows[rg] >> 1;
    const float* aptr = g_x1 + (size_t)tok * E_ + lcol;
    const float* bptr = eW + (size_t)e * E_ * E_ + (size_t)(n0 + lrow) * E_ + lcol;
    float acc[8][8] = {};
    gemm128_core(aptr, bptr, acc, As, Bs, lrow, lcol, tx, ty);
    int o0 = n0 + tx * 8;
    float bsr[8];
#pragma unroll
    for (int j = 0; j < 8; j++) bsr[j] = eB[e * E_ + o0 + j];
#pragma unroll
    for (int i = 0; i < 8; i++) {
        int rgi = r0 + ty * 8 + i;
        if (rgi < rend) {
            float gt = g_topgate[g_rows[rgi]];
            float4 w0 = make_float4((acc[i][0] + bsr[0]) * gt, (acc[i][1] + bsr[1]) * gt,
                                    (acc[i][2] + bsr[2]) * gt, (acc[i][3] + bsr[3]) * gt);
            float4 w1 = make_float4((acc[i][4] + bsr[4]) * gt, (acc[i][5] + bsr[5]) * gt,
                                    (acc[i][6] + bsr[6]) * gt, (acc[i][7] + bsr[7]) * gt);
            *(float4*)(g_eo + (size_t)rgi * E_ + o0)     = w0;
            *(float4*)(g_eo + (size_t)rgi * E_ + o0 + 4) = w1;
        }
    }
}

// ---------------- combine + LN2 -> d_out ----------------
__global__ __launch_bounds__(256) void moe_ln2_kernel(const float* __restrict__ w,
                                                      const float* __restrict__ bb,
                                                      float* __restrict__ out) {
    int t = blockIdx.x, tid = threadIdx.x;
    int p0 = g_slotpos[t * 2], p1 = g_slotpos[t * 2 + 1];
    float4 a  = ((const float4*)(g_x1 + (size_t)t * E_))[tid];
    float4 e0 = ((const float4*)(g_eo + (size_t)p0 * E_))[tid];
    float4 e1 = ((const float4*)(g_eo + (size_t)p1 * E_))[tid];
    float4 v = make_float4(a.x + e0.x + e1.x, a.y + e0.y + e1.y,
                           a.z + e0.z + e1.z, a.w + e0.w + e1.w);
    float s1 = v.x + v.y + v.z + v.w;
    float s2 = v.x * v.x + v.y * v.y + v.z * v.z + v.w * v.w;
    float2 tt = block_reduce_sum2(s1, s2);
    float mu = tt.x * (1.0f / E_);
    float var = tt.y * (1.0f / E_) - mu * mu;
    float inv = rsqrtf(var + 1e-5f);
    float4 wv = ((const float4*)w)[tid];
    float4 bv = ((const float4*)bb)[tid];
    float4 o;
    o.x = (v.x - mu) * inv * wv.x + bv.x;
    o.y = (v.y - mu) * inv * wv.y + bv.y;
    o.z = (v.z - mu) * inv * wv.z + bv.z;
    o.w = (v.w - mu) * inv * wv.w + bv.w;
    ((float4*)(out + (size_t)t * E_))[tid] = o;
}

// ---------------- launch ----------------
extern "C" void kernel_launch(void* const* d_in, const int* in_sizes, int n_in,
                              void* d_out, int out_size) {
    (void)in_sizes; (void)n_in; (void)out_size;
    const float* x      = (const float*)d_in[0];
    const float* in_w   = (const float*)d_in[1];
    const float* in_b   = (const float*)d_in[2];
    const float* ow     = (const float*)d_in[3];
    const float* ob     = (const float*)d_in[4];
    const float* gw     = (const float*)d_in[5];
    const float* gb     = (const float*)d_in[6];
    const float* ew     = (const float*)d_in[7];
    const float* eb     = (const float*)d_in[8];
    const float* ln1w   = (const float*)d_in[9];
    const float* ln1b   = (const float*)d_in[10];
    const float* ln2w   = (const float*)d_in[11];
    const float* ln2b   = (const float*)d_in[12];
    float* out = (float*)d_out;

    init_kernel<<<1, 32>>>();
    rope_kernel<<<(M_ * E_ / 2 + 255) / 256, 256>>>(x);
    qkv_gemm<<<dim3(24, 32), 256>>>(x, in_w, in_b);
    attn_kernel<<<dim3(S_ / 64, B_ * H_), 256>>>();
    outproj_gemm<<<dim3(8, 32), 256>>>(x, ow, ob);
    ln1_kernel<<<M_, 256>>>(ln1w, ln1b);
    gate_kernel<<<M_, 256>>>(gw, gb);
    offsets_kernel<<<1, 32>>>();
    scatter_kernel<<<NSLOT_ / 256, 256>>>();
    expert_gemm<<<dim3(8, 72), 256>>>(ew, eb);
    moe_ln2_kernel<<<M_, 256>>>(ln2w, ln2b, out);
}